// round 13
// baseline (speedup 1.0000x reference)
#include <cuda_runtime.h>
#include <cuda_fp16.h>
#include <math.h>
#include <stdint.h>

#define D 128
#define EPS 1e-5f
#define NODE_CAP 20096
#define E_MAX 640000

// TC kernel smem: 4 tiles (Ah, Al, W1h, W2h), 128 rows x 272 bytes
#define TILE_PITCH 272
#define TILE_BYTES_PAD (128 * TILE_PITCH)  // 34816
static const int TC_SMEM = 4 * TILE_BYTES_PAD;  // 139264

// ---------------- scratch ----------------
__device__ float g_t1[(size_t)E_MAX * D];
__device__ float g_v [(size_t)NODE_CAP * D];
__device__ float g_w [(size_t)NODE_CAP * D];
__device__ float g_P1[(size_t)NODE_CAP * D];
__device__ float g_P2[(size_t)NODE_CAP * D];
__device__ float g_aggT[(size_t)NODE_CAP * D];
__device__ float g_aggU[(size_t)NODE_CAP * D];
__device__ float g_deg[NODE_CAP];
__device__ float g_stats[5 * 2 * 128];
// prepped weights: 12 matrices, [n][k] fp16 128x128 = 32KB each
__device__ __align__(256) unsigned char g_wprep[12 * 32768];

// ---------------- helpers ----------------
__device__ __forceinline__ float elu1(float x) {
    float e;
    asm("ex2.approx.f32 %0, %1;" : "=f"(e) : "f"(x * 1.4426950408889634f));
    return x > 0.f ? x : (e - 1.0f);
}

__device__ __forceinline__ uint32_t smem_u32(const void* p) {
    uint32_t a;
    asm("{ .reg .u64 t; cvta.to.shared.u64 t, %1; cvt.u32.u64 %0, t; }" : "=r"(a) : "l"(p));
    return a;
}

#define CP_ASYNC16(dst, src) \
    asm volatile("cp.async.cg.shared.global [%0], [%1], 16;" :: "r"(dst), "l"(src))
#define CP_COMMIT() asm volatile("cp.async.commit_group;")
#define CP_WAIT1()  asm volatile("cp.async.wait_group 1;")
#define CP_WAIT0()  asm volatile("cp.async.wait_group 0;")

#define RED2(addr, a, b) \
    asm volatile("red.global.add.v2.f32 [%0], {%1, %2};" \
                 :: "l"(addr), "f"(a), "f"(b) : "memory")

// folded BN coeffs for one stage (call with tid<128, then sync)
__device__ __forceinline__ void bn_coeff(int stage, float cnt,
                                         const float* __restrict__ gv,
                                         const float* __restrict__ btv,
                                         int j, float& A, float& C) {
    float s1 = g_stats[stage * 256 + j];
    float s2 = g_stats[stage * 256 + 128 + j];
    float mu = s1 / cnt;
    float var = s2 / cnt - mu * mu;
    A = gv[j] * rsqrtf(var + EPS);
    C = btv[j] - mu * A;
}

// fp16 split: hi = RN_fp16(a); lo = RN_fp16(a - hi). Packed {even lo-half, odd hi-half}.
__device__ __forceinline__ void split2h(float a, float b, uint32_t& hi, uint32_t& lo) {
    __half ha = __float2half_rn(a), hb = __float2half_rn(b);
    float la = a - __half2float(ha);
    float lb = b - __half2float(hb);
    __half2 hp = __halves2half2(ha, hb);
    __half2 lp = __halves2half2(__float2half_rn(la), __float2half_rn(lb));
    hi = *reinterpret_cast<uint32_t*>(&hp);
    lo = *reinterpret_cast<uint32_t*>(&lp);
}

__device__ __forceinline__ void split_store8(const float* v, unsigned char* Ah,
                                             unsigned char* Al, uint32_t off) {
    uint32_t hw[4], lw[4];
#pragma unroll
    for (int i = 0; i < 4; i++) split2h(v[2 * i], v[2 * i + 1], hw[i], lw[i]);
    *reinterpret_cast<uint4*>(Ah + off) = make_uint4(hw[0], hw[1], hw[2], hw[3]);
    *reinterpret_cast<uint4*>(Al + off) = make_uint4(lw[0], lw[1], lw[2], lw[3]);
}

__device__ __forceinline__ void ldm4(uint32_t* r, uint32_t a) {
    asm volatile("ldmatrix.sync.aligned.m8n8.x4.shared.b16 {%0,%1,%2,%3}, [%4];"
                 : "=r"(r[0]), "=r"(r[1]), "=r"(r[2]), "=r"(r[3]) : "r"(a));
}

__device__ __forceinline__ void mma16816(float* c, const uint32_t* a, const uint32_t* b) {
    asm volatile(
        "mma.sync.aligned.m16n8k16.row.col.f32.f16.f16.f32 "
        "{%0,%1,%2,%3}, {%4,%5,%6,%7}, {%8,%9}, {%0,%1,%2,%3};"
        : "+f"(c[0]), "+f"(c[1]), "+f"(c[2]), "+f"(c[3])
        : "r"(a[0]), "r"(a[1]), "r"(a[2]), "r"(a[3]), "r"(b[0]), "r"(b[1]));
}

// 2-split fp16 warp GEMM, k-outer, warp tile m32 x n16 (32 warps cover 128x128)
// acc += Ah@Wh + Al@Wh  (W stored as RN fp16; x split exact to 2^-22)
__device__ __forceinline__ void warp_gemm2(uint32_t Ah, uint32_t Al, uint32_t Wh,
                                           int lane, int wm, int wn,
                                           float acc[2][2][4]) {
    const int arow = lane & 15;
    const int kA = ((lane >> 4) << 3) * 2;
    const int brow = ((lane >> 4) << 3) + (lane & 7);
    const int kB = (((lane >> 3) & 1) << 3) * 2;
    const uint32_t aoff0 = (uint32_t)((wm * 32 + arow) * TILE_PITCH) + kA;
    const uint32_t aoff1 = aoff0 + 16 * TILE_PITCH;
    const uint32_t boff = (uint32_t)((wn * 16 + brow) * TILE_PITCH) + kB;

#pragma unroll
    for (int k0 = 0; k0 < 128; k0 += 16) {
        uint32_t ah0[4], ah1[4], al0[4], al1[4], bh[4];
        ldm4(ah0, Ah + aoff0 + k0 * 2);
        ldm4(ah1, Ah + aoff1 + k0 * 2);
        ldm4(al0, Al + aoff0 + k0 * 2);
        ldm4(al1, Al + aoff1 + k0 * 2);
        ldm4(bh, Wh + boff + k0 * 2);
#pragma unroll
        for (int j = 0; j < 2; j++) {
            const uint32_t* bj = &bh[j * 2];
            mma16816(acc[0][j], ah0, bj);
            mma16816(acc[1][j], ah1, bj);
        }
#pragma unroll
        for (int j = 0; j < 2; j++) {
            const uint32_t* bj = &bh[j * 2];
            mma16816(acc[0][j], al0, bj);
            mma16816(acc[1][j], al1, bj);
        }
    }
}

// ---------------- weight prep: transpose + fp16 round (+ zero stats) -------
// m: 0:W1s0 1:W2s0 2:W1s1 3:W2s1 4:eW1a 5:eW2 6:W1s2 7:W2s2 8:W1s3 9:W2s3
//    10:eW1b 11:eW1c
__global__ void prep_weights(const float* __restrict__ W1s, const float* __restrict__ W2s,
                             const float* __restrict__ eW1, const float* __restrict__ eW2)
{
    if (blockIdx.x == 0) {
        for (int i = threadIdx.x; i < 5 * 2 * 128; i += 256) g_stats[i] = 0.f;
    }
    int idx = blockIdx.x * 256 + threadIdx.x;
    if (idx >= 12 * 16384) return;
    int m = idx >> 14;
    int e = idx & 16383;
    int n = e >> 7, k = e & 127;
    const float* W;
    switch (m) {
        case 0:  W = W1s; break;
        case 1:  W = W2s; break;
        case 2:  W = W1s + 16384; break;
        case 3:  W = W2s + 16384; break;
        case 4:  W = eW1; break;
        case 5:  W = eW2; break;
        case 6:  W = W1s + 2 * 16384; break;
        case 7:  W = W2s + 2 * 16384; break;
        case 8:  W = W1s + 3 * 16384; break;
        case 9:  W = W2s + 3 * 16384; break;
        case 10: W = eW1 + 128 * 128; break;
        default: W = eW1 + 256 * 128; break;
    }
    float v = W[k * 128 + n];
    *reinterpret_cast<__half*>(g_wprep + (size_t)m * 32768 + (size_t)e * 2) =
        __float2half_rn(v);
}

// ---------------- tensor-core fused 2-GEMM kernel, 1024 threads ------------
// modes: 0 raw; 1 x*BNa; 2 (BNa.A*x+BNb.A*x2)/deg+(BNa.C+BNb.C)*(deg>0); 3 BNa(x)+BNb(x2)
// wmode: 0 write out; 1 write out + red aggp[dst] + deg; 2 red aggp only
// NF: no bias, no ELU, GEMM1->out, GEMM2->out2, no stats
template <bool GATHER, bool NF>
__global__ void __launch_bounds__(1024, 1)
tc_mlp_tpl(const float* __restrict__ X, const float* __restrict__ X2,
           int m1, int m2,
           const float* __restrict__ B1, const float* __restrict__ B2,
           float* __restrict__ out, float* __restrict__ out2,
           int nrows, int mode, int stage,
           int sAi, const float* __restrict__ gA, const float* __restrict__ btA, float cntA,
           int sBi, const float* __restrict__ gB, const float* __restrict__ btB, float cntB,
           const float* __restrict__ degp,
           int wmode, float* __restrict__ aggp,
           const int* __restrict__ srcI, const int* __restrict__ dstI)
{
    extern __shared__ unsigned char smem[];
    unsigned char* Ah  = smem;
    unsigned char* Al  = smem + TILE_BYTES_PAD;
    unsigned char* W1h = smem + 2 * TILE_BYTES_PAD;
    unsigned char* W2h = smem + 3 * TILE_BYTES_PAD;
    __shared__ float sB1[128], sB2[128], sPA[128], sPC[128], sPA2[128], sPC2[128];
    __shared__ float sInv[128], sF[128], sSum[128], sSq[128];
    __shared__ int sSrc[128], sDst[128];

    const int tid = threadIdx.x, wid = tid >> 5, lane = tid & 31;
    const int wm = wid & 3, wn = wid >> 2;   // warp tile: rows 32*wm, cols 16*wn
    const int g = lane >> 2, tig = lane & 3;
    const int row0 = blockIdx.x * 128;

    // ---- async W1 prefetch (old group), W2 (young group) ----
    {
        const char* g1 = (const char*)(g_wprep + (size_t)m1 * 32768);
        const char* g2 = (const char*)(g_wprep + (size_t)m2 * 32768);
        {
            int idx = tid;
            uint32_t off = (uint32_t)((idx >> 4) * TILE_PITCH + (idx & 15) * 16);
            CP_ASYNC16(smem_u32(W1h + off), g1 + (size_t)idx * 16);
            idx = tid + 1024;
            off = (uint32_t)((idx >> 4) * TILE_PITCH + (idx & 15) * 16);
            CP_ASYNC16(smem_u32(W1h + off), g1 + (size_t)idx * 16);
        }
        CP_COMMIT();
        {
            int idx = tid;
            uint32_t off = (uint32_t)((idx >> 4) * TILE_PITCH + (idx & 15) * 16);
            CP_ASYNC16(smem_u32(W2h + off), g2 + (size_t)idx * 16);
            idx = tid + 1024;
            off = (uint32_t)((idx >> 4) * TILE_PITCH + (idx & 15) * 16);
            CP_ASYNC16(smem_u32(W2h + off), g2 + (size_t)idx * 16);
        }
        CP_COMMIT();
    }

    if (tid < 128) {
        if (!NF) { sB1[tid] = B1[tid]; sB2[tid] = B2[tid]; sSum[tid] = 0.f; sSq[tid] = 0.f; }
        if (mode >= 1) {
            float A, C;
            bn_coeff(sAi, cntA, gA, btA, tid, A, C);
            sPA[tid] = A; sPC[tid] = C;
        }
        if (mode >= 2) {
            float A, C;
            bn_coeff(sBi, cntB, gB, btB, tid, A, C);
            sPA2[tid] = A; sPC2[tid] = C;
            if (mode == 2) {
                int r = row0 + tid;
                float dg = (r < nrows) ? degp[r] : 0.f;
                sInv[tid] = 1.f / fmaxf(dg, 1.f);
                sF[tid] = dg > 0.f ? 1.f : 0.f;
            }
        }
        if (GATHER || wmode >= 1) {
            int gr = row0 + tid;
            sDst[tid] = (gr < nrows) ? dstI[gr] : 0;
            if (GATHER) sSrc[tid] = (gr < nrows) ? srcI[gr] : 0;
        }
    }
    __syncthreads();

    // ---- coalesced load + split A tile ----
#pragma unroll
    for (int t = 0; t < 2; t++) {
        int q = tid + 1024 * t;
        int r = q >> 4;
        int kp = (q & 15) << 3;
        int gr = row0 + r;
        float v[8];
        if (gr < nrows) {
            float4 a = *reinterpret_cast<const float4*>(X + (size_t)gr * D + kp);
            float4 b = *reinterpret_cast<const float4*>(X + (size_t)gr * D + kp + 4);
            v[0] = a.x; v[1] = a.y; v[2] = a.z; v[3] = a.w;
            v[4] = b.x; v[5] = b.y; v[6] = b.z; v[7] = b.w;
            if (mode == 1) {
#pragma unroll
                for (int i = 0; i < 8; i++) v[i] = v[i] * sPA[kp + i] + sPC[kp + i];
            } else if (mode >= 2) {
                float u[8];
                float4 c = *reinterpret_cast<const float4*>(X2 + (size_t)gr * D + kp);
                float4 d2 = *reinterpret_cast<const float4*>(X2 + (size_t)gr * D + kp + 4);
                u[0] = c.x; u[1] = c.y; u[2] = c.z; u[3] = c.w;
                u[4] = d2.x; u[5] = d2.y; u[6] = d2.z; u[7] = d2.w;
                if (mode == 2) {
                    float inv = sInv[r], f = sF[r];
#pragma unroll
                    for (int i = 0; i < 8; i++)
                        v[i] = (sPA[kp + i] * v[i] + sPA2[kp + i] * u[i]) * inv +
                               (sPC[kp + i] + sPC2[kp + i]) * f;
                } else {
#pragma unroll
                    for (int i = 0; i < 8; i++)
                        v[i] = sPA[kp + i] * v[i] + sPC[kp + i] +
                               sPA2[kp + i] * u[i] + sPC2[kp + i];
                }
            }
        } else {
#pragma unroll
            for (int i = 0; i < 8; i++) v[i] = 0.f;
        }
        split_store8(v, Ah, Al, (uint32_t)(r * TILE_PITCH + kp * 2));
    }
    CP_WAIT1();
    __syncthreads();

    const uint32_t uAh = smem_u32(Ah), uAl = smem_u32(Al);

    // ---- GEMM1 ----
    float acc[2][2][4];
#pragma unroll
    for (int i = 0; i < 2; i++)
#pragma unroll
        for (int j = 0; j < 2; j++) {
            int col = wn * 16 + j * 8 + 2 * tig;
            float b0 = NF ? 0.f : sB1[col];
            float b1v = NF ? 0.f : sB1[col + 1];
            acc[i][j][0] = b0; acc[i][j][1] = b1v;
            acc[i][j][2] = b0; acc[i][j][3] = b1v;
        }
    warp_gemm2(uAh, uAl, smem_u32(W1h), lane, wm, wn, acc);

    if (NF) {
#pragma unroll
        for (int i = 0; i < 2; i++) {
            int r0 = wm * 32 + i * 16 + g;
            int r1 = r0 + 8;
            int gr0 = row0 + r0, gr1 = row0 + r1;
#pragma unroll
            for (int j = 0; j < 2; j++) {
                int col = wn * 16 + j * 8 + 2 * tig;
                if (gr0 < nrows)
                    *reinterpret_cast<float2*>(out + (size_t)gr0 * D + col) =
                        make_float2(acc[i][j][0], acc[i][j][1]);
                if (gr1 < nrows)
                    *reinterpret_cast<float2*>(out + (size_t)gr1 * D + col) =
                        make_float2(acc[i][j][2], acc[i][j][3]);
            }
        }
    } else {
        __syncthreads();  // all warps done reading Ah/Al before rewrite
#pragma unroll
        for (int i = 0; i < 2; i++) {
            int r0 = wm * 32 + i * 16 + g;
            int r1 = r0 + 8;
#pragma unroll
            for (int j = 0; j < 2; j++) {
                int col = wn * 16 + j * 8 + 2 * tig;
                float v0 = acc[i][j][0], v1 = acc[i][j][1];
                float v2 = acc[i][j][2], v3 = acc[i][j][3];
                if (GATHER) {
                    const float2 p1a = *reinterpret_cast<const float2*>(g_P1 + (size_t)sSrc[r0] * D + col);
                    const float2 p2a = *reinterpret_cast<const float2*>(g_P2 + (size_t)sDst[r0] * D + col);
                    const float2 p1b = *reinterpret_cast<const float2*>(g_P1 + (size_t)sSrc[r1] * D + col);
                    const float2 p2b = *reinterpret_cast<const float2*>(g_P2 + (size_t)sDst[r1] * D + col);
                    v0 += p1a.x + p2a.x; v1 += p1a.y + p2a.y;
                    v2 += p1b.x + p2b.x; v3 += p1b.y + p2b.y;
                }
                v0 = elu1(v0); v1 = elu1(v1); v2 = elu1(v2); v3 = elu1(v3);
                uint32_t hi, lo;
                split2h(v0, v1, hi, lo);
                *reinterpret_cast<uint32_t*>(Ah + r0 * TILE_PITCH + col * 2) = hi;
                *reinterpret_cast<uint32_t*>(Al + r0 * TILE_PITCH + col * 2) = lo;
                split2h(v2, v3, hi, lo);
                *reinterpret_cast<uint32_t*>(Ah + r1 * TILE_PITCH + col * 2) = hi;
                *reinterpret_cast<uint32_t*>(Al + r1 * TILE_PITCH + col * 2) = lo;
            }
        }
    }
    CP_WAIT0();       // W2 resident
    __syncthreads();

    // ---- GEMM2 ----
#pragma unroll
    for (int i = 0; i < 2; i++)
#pragma unroll
        for (int j = 0; j < 2; j++) {
            int col = wn * 16 + j * 8 + 2 * tig;
            float b0 = NF ? 0.f : sB2[col];
            float b1v = NF ? 0.f : sB2[col + 1];
            acc[i][j][0] = b0; acc[i][j][1] = b1v;
            acc[i][j][2] = b0; acc[i][j][3] = b1v;
        }
    warp_gemm2(uAh, uAl, smem_u32(W2h), lane, wm, wn, acc);

    if (NF) {
#pragma unroll
        for (int i = 0; i < 2; i++) {
            int r0 = wm * 32 + i * 16 + g;
            int r1 = r0 + 8;
            int gr0 = row0 + r0, gr1 = row0 + r1;
#pragma unroll
            for (int j = 0; j < 2; j++) {
                int col = wn * 16 + j * 8 + 2 * tig;
                if (gr0 < nrows)
                    *reinterpret_cast<float2*>(out2 + (size_t)gr0 * D + col) =
                        make_float2(acc[i][j][0], acc[i][j][1]);
                if (gr1 < nrows)
                    *reinterpret_cast<float2*>(out2 + (size_t)gr1 * D + col) =
                        make_float2(acc[i][j][2], acc[i][j][3]);
            }
        }
        return;
    }

    // ---- epilogue2: h2 = elu(acc) -> gmem / red-scatter; stats via butterfly
    float sc[2][2], sq[2][2];
#pragma unroll
    for (int j = 0; j < 2; j++) {
        sc[j][0] = sc[j][1] = 0.f;
        sq[j][0] = sq[j][1] = 0.f;
    }
#pragma unroll
    for (int i = 0; i < 2; i++) {
        int r0 = wm * 32 + i * 16 + g;
        int r1 = r0 + 8;
        int gr0 = row0 + r0, gr1 = row0 + r1;
        bool va = gr0 < nrows, vb = gr1 < nrows;
#pragma unroll
        for (int j = 0; j < 2; j++) {
            int col = wn * 16 + j * 8 + 2 * tig;
            float v0 = va ? elu1(acc[i][j][0]) : 0.f;
            float v1 = va ? elu1(acc[i][j][1]) : 0.f;
            float v2 = vb ? elu1(acc[i][j][2]) : 0.f;
            float v3 = vb ? elu1(acc[i][j][3]) : 0.f;
            sc[j][0] += v0 + v2; sc[j][1] += v1 + v3;
            sq[j][0] += v0 * v0 + v2 * v2; sq[j][1] += v1 * v1 + v3 * v3;
            if (wmode <= 1) {
                if (va) *reinterpret_cast<float2*>(out + (size_t)gr0 * D + col) = make_float2(v0, v1);
                if (vb) *reinterpret_cast<float2*>(out + (size_t)gr1 * D + col) = make_float2(v2, v3);
            }
            if (wmode >= 1) {
                if (va) RED2(aggp + (size_t)sDst[r0] * D + col, v0, v1);
                if (vb) RED2(aggp + (size_t)sDst[r1] * D + col, v2, v3);
            }
        }
    }
    if (wmode == 1 && tid < 128 && (row0 + tid) < nrows) {
        asm volatile("red.global.add.f32 [%0], %1;"
                     :: "l"(g_deg + sDst[tid]), "f"(1.f) : "memory");
    }
    // butterfly over g bits (4, 8, 16): sum warp's 32 rows per column
#pragma unroll
    for (int m = 4; m <= 16; m <<= 1)
#pragma unroll
        for (int j = 0; j < 2; j++)
#pragma unroll
            for (int k = 0; k < 2; k++) {
                sc[j][k] += __shfl_xor_sync(0xFFFFFFFFu, sc[j][k], m);
                sq[j][k] += __shfl_xor_sync(0xFFFFFFFFu, sq[j][k], m);
            }
    if (lane < 4) {
#pragma unroll
        for (int j = 0; j < 2; j++) {
            int col = wn * 16 + j * 8 + 2 * lane;
            atomicAdd(&sSum[col], sc[j][0]);
            atomicAdd(&sSum[col + 1], sc[j][1]);
            atomicAdd(&sSq[col], sq[j][0]);
            atomicAdd(&sSq[col + 1], sq[j][1]);
        }
    }
    __syncthreads();
    if (tid < 128) {
        atomicAdd(&g_stats[stage * 256 + tid], sSum[tid]);
        atomicAdd(&g_stats[stage * 256 + 128 + tid], sSq[tid]);
    }
}

// final in-place BN on output (stage-4 coeffs computed per block)
__global__ void norm_out_kernel(float* __restrict__ out, int n4, float cnt,
                                const float* __restrict__ eg,
                                const float* __restrict__ ebt)
{
    __shared__ float sA[128], sC[128];
    if (threadIdx.x < 128) {
        float A, C;
        bn_coeff(4, cnt, eg, ebt, threadIdx.x, A, C);
        sA[threadIdx.x] = A; sC[threadIdx.x] = C;
    }
    __syncthreads();
    int idx = blockIdx.x * blockDim.x + threadIdx.x;
    if (idx >= n4) return;
    int cv = idx & 31;
    float4 A = reinterpret_cast<const float4*>(sA)[cv];
    float4 C = reinterpret_cast<const float4*>(sC)[cv];
    float4 v = reinterpret_cast<float4*>(out)[idx];
    v.x = v.x * A.x + C.x;
    v.y = v.y * A.y + C.y;
    v.z = v.z * A.z + C.z;
    v.w = v.w * A.w + C.w;
    reinterpret_cast<float4*>(out)[idx] = v;
}

// ---------------- host orchestration ----------------
extern "C" void kernel_launch(void* const* d_in, const int* in_sizes, int n_in,
                              void* d_out, int out_size)
{
    if (n_in < 15) return;
    const float* edata = (const float*)d_in[0];
    const int*   src   = (const int*)d_in[1];
    const int*   dst   = (const int*)d_in[2];
    int w = (n_in >= 16) ? 4 : 3;
    const float* W1s = (const float*)d_in[w + 0];
    const float* b1s = (const float*)d_in[w + 1];
    const float* W2s = (const float*)d_in[w + 2];
    const float* b2s = (const float*)d_in[w + 3];
    const float* gs  = (const float*)d_in[w + 4];
    const float* bts = (const float*)d_in[w + 5];
    const float* eW1 = (const float*)d_in[w + 6];
    const float* eb1 = (const float*)d_in[w + 7];
    const float* eW2 = (const float*)d_in[w + 8];
    const float* eb2 = (const float*)d_in[w + 9];
    const float* eg  = (const float*)d_in[w + 10];
    const float* ebt = (const float*)d_in[w + 11];

    int E = in_sizes[0] / D;
    int N = 20000;

    float *p_t1, *p_v, *p_w2, *p_P1, *p_P2, *p_aggT, *p_aggU, *p_deg;
    cudaGetSymbolAddress((void**)&p_t1, g_t1);
    cudaGetSymbolAddress((void**)&p_v, g_v);
    cudaGetSymbolAddress((void**)&p_w2, g_w);
    cudaGetSymbolAddress((void**)&p_P1, g_P1);
    cudaGetSymbolAddress((void**)&p_P2, g_P2);
    cudaGetSymbolAddress((void**)&p_aggT, g_aggT);
    cudaGetSymbolAddress((void**)&p_aggU, g_aggU);
    cudaGetSymbolAddress((void**)&p_deg, g_deg);

    cudaFuncSetAttribute(tc_mlp_tpl<false, false>, cudaFuncAttributeMaxDynamicSharedMemorySize, TC_SMEM);
    cudaFuncSetAttribute(tc_mlp_tpl<false, true>,  cudaFuncAttributeMaxDynamicSharedMemorySize, TC_SMEM);
    cudaFuncSetAttribute(tc_mlp_tpl<true, false>,  cudaFuncAttributeMaxDynamicSharedMemorySize, TC_SMEM);

    cudaMemsetAsync(p_aggT, 0, (size_t)NODE_CAP * D * sizeof(float), 0);
    cudaMemsetAsync(p_aggU, 0, (size_t)NODE_CAP * D * sizeof(float), 0);
    cudaMemsetAsync(p_deg, 0, NODE_CAP * sizeof(float), 0);

    int egrid = (E + 127) / 128;
    int ngrid = (N + 127) / 128;

    // weight prep: 12 matrices, fp16 RN (also zeroes g_stats)
    prep_weights<<<(12 * 16384 + 255) / 256, 256>>>(W1s, W2s, eW1, eW2);

    // edge MLP0: write t1 + raw-scatter to aggT + deg   (stage 0)
    tc_mlp_tpl<false, false><<<egrid, 1024, TC_SMEM>>>(
        edata, nullptr, 0, 1, b1s, b2s, p_t1, nullptr, E, 0, 0,
        0, nullptr, nullptr, 0.f, 0, nullptr, nullptr, 0.f, nullptr,
        1, p_aggT, nullptr, dst);
    // edge MLP1 (input = BN0(t1)): no gmem write; raw-scatter u to aggU (stage 1)
    tc_mlp_tpl<false, false><<<egrid, 1024, TC_SMEM>>>(
        p_t1, nullptr, 2, 3, b1s + 128, b2s + 128, nullptr, nullptr, E, 1, 1,
        0, gs, bts, (float)E, 0, nullptr, nullptr, 0.f, nullptr,
        2, p_aggU, nullptr, dst);
    // node MLP2: input = (A0*aggT + A1*aggU)/deg + (C0+C1)   (stage 2)
    tc_mlp_tpl<false, false><<<ngrid, 1024, TC_SMEM>>>(
        p_aggT, p_aggU, 6, 7, b1s + 256, b2s + 256, p_v, nullptr, N, 2, 2,
        0, gs, bts, (float)E, 1, gs + 128, bts + 128, (float)E, p_deg,
        0, nullptr, nullptr, nullptr);
    // node MLP3 (input = BN2(v))   (stage 3)
    tc_mlp_tpl<false, false><<<ngrid, 1024, TC_SMEM>>>(
        p_v, nullptr, 8, 9, b1s + 384, b2s + 384, p_w2, nullptr, N, 1, 3,
        2, gs + 256, bts + 256, (float)N, 0, nullptr, nullptr, 0.f, nullptr,
        0, nullptr, nullptr, nullptr);
    // node final: h_n = BN2(v)+BN3(w); P1 = h@eW1b, P2 = h@eW1c  (NF path)
    tc_mlp_tpl<false, true><<<ngrid, 1024, TC_SMEM>>>(
        p_v, p_w2, 10, 11, nullptr, nullptr, p_P1, p_P2, N, 3, 0,
        2, gs + 256, bts + 256, (float)N, 3, gs + 384, bts + 384, (float)N, nullptr,
        0, nullptr, nullptr, nullptr);
    // final edge MLP (with gathers) -> d_out (pre-BN)   (stage 4)
    tc_mlp_tpl<true, false><<<egrid, 1024, TC_SMEM>>>(
        edata, nullptr, 4, 5, eb1, eb2, (float*)d_out, nullptr, E, 0, 4,
        0, nullptr, nullptr, 0.f, 0, nullptr, nullptr, 0.f, nullptr,
        0, nullptr, src, dst);
    // final in-place BN
    int n4 = E * (D / 4);
    norm_out_kernel<<<(n4 + 255) / 256, 256>>>((float*)d_out, n4, (float)E, eg, ebt);
}